// round 1
// baseline (speedup 1.0000x reference)
#include <cuda_runtime.h>
#include <math.h>
#include <stdint.h>

#define NNODES 50000
#define NEDGES 800000
#define FDIM 128
#define HDIM 128
#define ODIM 128
#define KOBS 4
#define ZDIM 512   /* K*H */
#define MID  256   /* 2*H */

// ---------------- scratch (device globals; no allocation allowed) ----------
__device__ __align__(16) float g_h  [(size_t)NNODES * HDIM];
__device__ __align__(16) float g_hw [(size_t)NNODES * HDIM];
__device__ __align__(16) float g_agg[(size_t)NNODES * ZDIM];
__device__ __align__(16) float g_z1 [(size_t)NNODES * MID];
__device__ double g_colsum  [ZDIM];
__device__ double g_colsumsq[ZDIM];
__device__ float  g_scale[ZDIM];
__device__ float  g_shift[ZDIM];
__device__ unsigned int g_distmax_bits;

// ---------------- zero kernels ---------------------------------------------
__global__ void k_zero_misc() {
    int t = threadIdx.x;
    if (t == 0) g_distmax_bits = 0u;
    if (t < ZDIM) { g_colsum[t] = 0.0; g_colsumsq[t] = 0.0; }
}

__global__ void k_zero_agg() {
    size_t i = (size_t)blockIdx.x * blockDim.x + threadIdx.x;
    size_t total = (size_t)NNODES * ZDIM / 4;
    float4 z = make_float4(0.f, 0.f, 0.f, 0.f);
    for (; i < total; i += (size_t)gridDim.x * blockDim.x)
        ((float4*)g_agg)[i] = z;
}

// ---------------- SGEMM: C[r,c] = sum_k A[r,k]*W[c,k] + bias[c] ------------
// A: [nrows, kdim] row-major; W: [mcols, kdim] row-major (i.e. computes A @ W^T)
// 128x128 tile, BK=16, 256 threads, 8x8 per-thread microtile.
__global__ void __launch_bounds__(256)
k_sgemm(const float* __restrict__ A, const float* __restrict__ W,
        const float* __restrict__ bias, float* __restrict__ C,
        int nrows, int kdim, int mcols, int do_relu)
{
    __shared__ float As[16][132];
    __shared__ float Ws[16][132];
    const int tid  = threadIdx.x;
    const int row0 = blockIdx.y * 128;
    const int col0 = blockIdx.x * 128;
    const int tx = tid & 15;
    const int ty = tid >> 4;

    float acc[8][8];
#pragma unroll
    for (int i = 0; i < 8; i++)
#pragma unroll
        for (int j = 0; j < 8; j++) acc[i][j] = 0.f;

    for (int k0 = 0; k0 < kdim; k0 += 16) {
#pragma unroll
        for (int t = 0; t < 2; t++) {
            int l  = tid + t * 256;        // 0..511
            int m  = l >> 2;               // 0..127
            int kv = (l & 3) * 4;          // 0,4,8,12
            float4 v = make_float4(0.f, 0.f, 0.f, 0.f);
            int row = row0 + m;
            if (row < nrows)
                v = *(const float4*)&A[(size_t)row * kdim + k0 + kv];
            As[kv + 0][m] = v.x; As[kv + 1][m] = v.y;
            As[kv + 2][m] = v.z; As[kv + 3][m] = v.w;
            float4 w = *(const float4*)&W[(size_t)(col0 + m) * kdim + k0 + kv];
            Ws[kv + 0][m] = w.x; Ws[kv + 1][m] = w.y;
            Ws[kv + 2][m] = w.z; Ws[kv + 3][m] = w.w;
        }
        __syncthreads();
#pragma unroll
        for (int kk = 0; kk < 16; kk++) {
            float a[8], b[8];
            *(float4*)&a[0] = *(const float4*)&As[kk][ty * 8];
            *(float4*)&a[4] = *(const float4*)&As[kk][ty * 8 + 4];
            *(float4*)&b[0] = *(const float4*)&Ws[kk][tx * 8];
            *(float4*)&b[4] = *(const float4*)&Ws[kk][tx * 8 + 4];
#pragma unroll
            for (int i = 0; i < 8; i++)
#pragma unroll
                for (int j = 0; j < 8; j++)
                    acc[i][j] += a[i] * b[j];
        }
        __syncthreads();
    }

#pragma unroll
    for (int i = 0; i < 8; i++) {
        int row = row0 + ty * 8 + i;
        if (row >= nrows) break;
#pragma unroll
        for (int j = 0; j < 8; j++) {
            int col = col0 + tx * 8 + j;
            float v = acc[i][j] + bias[col];
            if (do_relu) v = fmaxf(v, 0.f);
            C[(size_t)row * mcols + col] = v;
        }
    }
}

// ---------------- max distance over edges ----------------------------------
__global__ void k_distmax(const int* __restrict__ ei, const float* __restrict__ pos)
{
    int i = blockIdx.x * blockDim.x + threadIdx.x;
    float m = 0.f;
    for (; i < NEDGES; i += gridDim.x * blockDim.x) {
        int s = ei[i], d = ei[NEDGES + i];
        float ax = pos[3 * s + 0] - pos[3 * d + 0];
        float ay = pos[3 * s + 1] - pos[3 * d + 1];
        float az = pos[3 * s + 2] - pos[3 * d + 2];
        m = fmaxf(m, sqrtf(ax * ax + ay * ay + az * az));
    }
#pragma unroll
    for (int o = 16; o; o >>= 1) m = fmaxf(m, __shfl_xor_sync(0xffffffffu, m, o));
    if ((threadIdx.x & 31) == 0) atomicMax(&g_distmax_bits, __float_as_uint(m));
}

// ---------------- edge scatter: agg[dst, k*128+f] += ab_k * hw[src, f] ------
__global__ void __launch_bounds__(256)
k_scatter(const int* __restrict__ ei, const float* __restrict__ pos,
          const float* __restrict__ vfp, const float* __restrict__ vparams)
{
    int e = (int)(((size_t)blockIdx.x * blockDim.x + threadIdx.x) >> 5);
    if (e >= NEDGES) return;
    const int lane = threadIdx.x & 31;

    int s = __ldg(&ei[e]);
    int d = __ldg(&ei[NEDGES + e]);

    float ax = pos[3 * s + 0] - pos[3 * d + 0];
    float ay = pos[3 * s + 1] - pos[3 * d + 1];
    float az = pos[3 * s + 2] - pos[3 * d + 2];
    float dist = sqrtf(ax * ax + ay * ay + az * az);
    float dmax = __uint_as_float(g_distmax_bits);
    float r    = dist / dmax;
    float inv  = 1.f / (dist + 1e-8f);
    float dsum = (ax + ay + az) * inv;
    float vf   = vfp[0];

    float ab[KOBS];
#pragma unroll
    for (int k = 0; k < KOBS; k++) {
        float v  = vf * fminf(r, vparams[k]);
        float g2 = 1.f - v * v + 1e-8f;
        // ab = 1/(gamma*(1+v*dsum)) with gamma = 1/sqrt(g2)
        ab[k] = sqrtf(g2) / (1.f + v * dsum);
    }

    const float4 hv = *(const float4*)&g_hw[(size_t)s * HDIM + lane * 4];
    float* base = &g_agg[(size_t)d * ZDIM + lane * 4];
#pragma unroll
    for (int k = 0; k < KOBS; k++) {
        float mx = ab[k] * hv.x, my = ab[k] * hv.y;
        float mz = ab[k] * hv.z, mw = ab[k] * hv.w;
        asm volatile("red.global.add.v4.f32 [%0], {%1, %2, %3, %4};"
                     :: "l"(base + k * HDIM), "f"(mx), "f"(my), "f"(mz), "f"(mw)
                     : "memory");
    }
}

// ---------------- BN column stats (mean/var over nodes) ---------------------
__global__ void k_colstats()
{
    int col = blockIdx.x * blockDim.x + threadIdx.x;    // grid.x = 2, block 256
    int r0 = blockIdx.y * 500;                          // grid.y = 100
    int r1 = r0 + 500; if (r1 > NNODES) r1 = NNODES;
    float s = 0.f, s2 = 0.f;
    for (int r = r0; r < r1; r++) {
        float v = g_agg[(size_t)r * ZDIM + col];
        s += v; s2 += v * v;
    }
    atomicAdd(&g_colsum[col],   (double)s);
    atomicAdd(&g_colsumsq[col], (double)s2);
}

__global__ void k_bnfinal(const float* __restrict__ bn_gamma,
                          const float* __restrict__ bn_beta)
{
    int c = blockIdx.x * blockDim.x + threadIdx.x;
    if (c >= ZDIM) return;
    float mean = (float)(g_colsum[c] * (1.0 / NNODES));
    float var  = (float)(g_colsumsq[c] * (1.0 / NNODES)) - mean * mean;
    float invs = 1.f / sqrtf(var + 1e-5f);
    float sc = invs * bn_gamma[c];
    g_scale[c] = sc;
    g_shift[c] = bn_beta[c] - mean * sc;
}

// ---------------- BN + relu + attention (in place on agg) -------------------
__global__ void k_bnact(const float* __restrict__ att)
{
    size_t i = (size_t)blockIdx.x * blockDim.x + threadIdx.x;
    size_t total = (size_t)NNODES * ZDIM / 4;
    for (; i < total; i += (size_t)gridDim.x * blockDim.x) {
        int c = (int)((i * 4) & (ZDIM - 1));
        float4 v = ((float4*)g_agg)[i];
        v.x = fmaxf(v.x * g_scale[c + 0] + g_shift[c + 0], 0.f) * att[c + 0];
        v.y = fmaxf(v.y * g_scale[c + 1] + g_shift[c + 1], 0.f) * att[c + 1];
        v.z = fmaxf(v.z * g_scale[c + 2] + g_shift[c + 2], 0.f) * att[c + 2];
        v.w = fmaxf(v.w * g_scale[c + 3] + g_shift[c + 3], 0.f) * att[c + 3];
        ((float4*)g_agg)[i] = v;
    }
}

// ---------------- LayerNorm (per row of z1 [N,256]) + relu, in place --------
__global__ void k_lnrelu(const float* __restrict__ gam, const float* __restrict__ bet)
{
    int row = blockIdx.x * (blockDim.x >> 5) + (threadIdx.x >> 5);
    if (row >= NNODES) return;
    int lane = threadIdx.x & 31;
    float* p = g_z1 + (size_t)row * MID;
    float v[8];
    float s = 0.f;
#pragma unroll
    for (int i = 0; i < 8; i++) { v[i] = p[lane + 32 * i]; s += v[i]; }
#pragma unroll
    for (int o = 16; o; o >>= 1) s += __shfl_xor_sync(0xffffffffu, s, o);
    float mean = s * (1.f / MID);
    float q = 0.f;
#pragma unroll
    for (int i = 0; i < 8; i++) { float t = v[i] - mean; q += t * t; }
#pragma unroll
    for (int o = 16; o; o >>= 1) q += __shfl_xor_sync(0xffffffffu, q, o);
    float inv = rsqrtf(q * (1.f / MID) + 1e-5f);
#pragma unroll
    for (int i = 0; i < 8; i++) {
        int c = lane + 32 * i;
        p[c] = fmaxf((v[i] - mean) * inv * gam[c] + bet[c], 0.f);
    }
}

// ---------------- launch -----------------------------------------------------
extern "C" void kernel_launch(void* const* d_in, const int* in_sizes, int n_in,
                              void* d_out, int out_size)
{
    const float* x        = (const float*)d_in[0];
    const int*   ei       = (const int*)  d_in[1];
    const float* pos      = (const float*)d_in[2];
    const float* W_ft     = (const float*)d_in[3];
    const float* b_ft     = (const float*)d_in[4];
    const float* W_conv   = (const float*)d_in[5];
    const float* b_conv   = (const float*)d_in[6];
    const float* vf       = (const float*)d_in[7];
    const float* vparams  = (const float*)d_in[8];
    const float* bn_gamma = (const float*)d_in[9];
    const float* bn_beta  = (const float*)d_in[10];
    const float* att      = (const float*)d_in[11];
    const float* W1       = (const float*)d_in[12];
    const float* b1       = (const float*)d_in[13];
    const float* ln_g     = (const float*)d_in[14];
    const float* ln_b     = (const float*)d_in[15];
    const float* W2       = (const float*)d_in[16];
    const float* b2       = (const float*)d_in[17];
    float* out = (float*)d_out;

    float *ph, *phw, *pagg, *pz1;
    cudaGetSymbolAddress((void**)&ph,   g_h);
    cudaGetSymbolAddress((void**)&phw,  g_hw);
    cudaGetSymbolAddress((void**)&pagg, g_agg);
    cudaGetSymbolAddress((void**)&pz1,  g_z1);

    // zero accumulators
    k_zero_misc<<<1, 512>>>();
    k_zero_agg<<<12800, 256>>>();

    // feature transform + conv linear (applied per node; gather commutes)
    {
        dim3 g(HDIM / 128, (NNODES + 127) / 128);
        k_sgemm<<<g, 256>>>(x, W_ft, b_ft, ph, NNODES, FDIM, HDIM, 1);
        k_sgemm<<<g, 256>>>(ph, W_conv, b_conv, phw, NNODES, HDIM, HDIM, 0);
    }

    // edge geometry: global max distance, then scatter with aberration factors
    k_distmax<<<1024, 256>>>(ei, pos);
    {
        int blocks = (NEDGES + 7) / 8;   // one warp per edge, 8 warps/block
        k_scatter<<<blocks, 256>>>(ei, pos, vf, vparams);
    }

    // BatchNorm over nodes per (observer,feature) column + relu + attention
    {
        dim3 g(2, 100);
        k_colstats<<<g, 256>>>();
    }
    k_bnfinal<<<2, 256>>>(bn_gamma, bn_beta);
    k_bnact<<<8192, 256>>>(att);

    // MLP head: [N,512] @ W1^T -> LN -> relu -> @ W2^T
    {
        dim3 g(MID / 128, (NNODES + 127) / 128);
        k_sgemm<<<g, 256>>>(pagg, W1, b1, pz1, NNODES, ZDIM, MID, 0);
    }
    k_lnrelu<<<(NNODES + 7) / 8, 256>>>(ln_g, ln_b);
    {
        dim3 g(ODIM / 128, (NNODES + 127) / 128);
        k_sgemm<<<g, 256>>>(pz1, W2, b2, out, NNODES, MID, ODIM, 0);
    }
}

// round 2
// speedup vs baseline: 1.7493x; 1.7493x over previous
#include <cuda_runtime.h>
#include <math.h>
#include <stdint.h>

#define NNODES 50000
#define NEDGES 800000
#define FDIM 128
#define HDIM 128
#define ODIM 128
#define KOBS 4
#define ZDIM 512   /* K*H */
#define MID  256   /* 2*H */

// ---------------- scratch (device globals; no allocation allowed) ----------
__device__ __align__(16) float g_h  [(size_t)NNODES * HDIM];
__device__ __align__(16) float g_hw [(size_t)NNODES * HDIM];
__device__ __align__(16) float g_agg[(size_t)NNODES * ZDIM];
__device__ __align__(16) float g_z1 [(size_t)NNODES * MID];
__device__ double g_colsum  [ZDIM];
__device__ double g_colsumsq[ZDIM];
__device__ float  g_scale[ZDIM];   // bn scale * attention
__device__ float  g_shift[ZDIM];   // bn shift * attention
__device__ unsigned int g_distmax_bits;

// ---------------- zero kernels ---------------------------------------------
__global__ void k_zero_misc() {
    int t = threadIdx.x;
    if (t == 0) g_distmax_bits = 0u;
    if (t < ZDIM) { g_colsum[t] = 0.0; g_colsumsq[t] = 0.0; }
}

__global__ void k_zero_agg() {
    size_t i = (size_t)blockIdx.x * blockDim.x + threadIdx.x;
    size_t total = (size_t)NNODES * ZDIM / 4;
    float4 z = make_float4(0.f, 0.f, 0.f, 0.f);
    for (; i < total; i += (size_t)gridDim.x * blockDim.x)
        ((float4*)g_agg)[i] = z;
}

// ---------------- tf32 tensor-core GEMM ------------------------------------
// C[r,c] = sum_k A[r,k] * W[c,k] + bias[c]       (A @ W^T + b)
// A [nrows, kdim] row-major, W [mcols, kdim] row-major.
// CTA tile 128x128, BK=32, 8 warps each computing 64x32 via m16n8k8 tf32 mma.
// amode==1: A elements transformed on load: relu(a*g_scale[k] + g_shift[k])
// (used to fuse BatchNorm+relu+attention into the W1 GEMM).
__device__ __forceinline__ float to_tf32(float x) {
    float r;
    asm("cvt.rna.tf32.f32 %0, %1;" : "=f"(r) : "f"(x));
    return r;
}

#define ASTRIDE 36   /* pad: bank index = (4*row + k) % 32, conflict-free */

__global__ void __launch_bounds__(256, 2)
k_gemm_tf32(const float* __restrict__ A, const float* __restrict__ W,
            const float* __restrict__ bias, float* __restrict__ C,
            int nrows, int kdim, int mcols, int do_relu, int amode)
{
    __shared__ float As[128][ASTRIDE];
    __shared__ float Ws[128][ASTRIDE];
    const int tid  = threadIdx.x;
    const int warp = tid >> 5;
    const int lane = tid & 31;
    const int row0 = blockIdx.y * 128;
    const int col0 = blockIdx.x * 128;
    const int mw = (warp & 1) * 64;
    const int nw = (warp >> 1) * 32;
    const int gq = lane >> 2;      // group id 0..7
    const int tq = lane & 3;       // thread-in-group 0..3

    float c[4][4][4];
#pragma unroll
    for (int mi = 0; mi < 4; mi++)
#pragma unroll
        for (int ni = 0; ni < 4; ni++)
#pragma unroll
            for (int q = 0; q < 4; q++) c[mi][ni][q] = 0.f;

    for (int k0 = 0; k0 < kdim; k0 += 32) {
        // ---- load A tile (with optional BN transform) ----
#pragma unroll
        for (int t = 0; t < 4; t++) {
            int idx = tid + t * 256;     // 0..1023
            int r   = idx >> 3;          // 0..127
            int kv  = (idx & 7) * 4;     // 0,4,...,28
            float4 v = make_float4(0.f, 0.f, 0.f, 0.f);
            if (row0 + r < nrows)
                v = *(const float4*)&A[(size_t)(row0 + r) * kdim + k0 + kv];
            if (amode) {
                int cc = k0 + kv;
                v.x = fmaxf(fmaf(v.x, g_scale[cc + 0], g_shift[cc + 0]), 0.f);
                v.y = fmaxf(fmaf(v.y, g_scale[cc + 1], g_shift[cc + 1]), 0.f);
                v.z = fmaxf(fmaf(v.z, g_scale[cc + 2], g_shift[cc + 2]), 0.f);
                v.w = fmaxf(fmaf(v.w, g_scale[cc + 3], g_shift[cc + 3]), 0.f);
            }
            As[r][kv + 0] = to_tf32(v.x);
            As[r][kv + 1] = to_tf32(v.y);
            As[r][kv + 2] = to_tf32(v.z);
            As[r][kv + 3] = to_tf32(v.w);
        }
        // ---- load W tile ----
#pragma unroll
        for (int t = 0; t < 4; t++) {
            int idx = tid + t * 256;
            int r   = idx >> 3;
            int kv  = (idx & 7) * 4;
            float4 v = *(const float4*)&W[(size_t)(col0 + r) * kdim + k0 + kv];
            Ws[r][kv + 0] = to_tf32(v.x);
            Ws[r][kv + 1] = to_tf32(v.y);
            Ws[r][kv + 2] = to_tf32(v.z);
            Ws[r][kv + 3] = to_tf32(v.w);
        }
        __syncthreads();

#pragma unroll
        for (int j = 0; j < 4; j++) {
            const int kk = j * 8;
            uint32_t a[4][4], b[4][2];
#pragma unroll
            for (int mi = 0; mi < 4; mi++) {
                int r = mw + mi * 16 + gq;
                a[mi][0] = __float_as_uint(As[r    ][kk + tq]);
                a[mi][1] = __float_as_uint(As[r + 8][kk + tq]);
                a[mi][2] = __float_as_uint(As[r    ][kk + tq + 4]);
                a[mi][3] = __float_as_uint(As[r + 8][kk + tq + 4]);
            }
#pragma unroll
            for (int ni = 0; ni < 4; ni++) {
                int cc = nw + ni * 8 + gq;
                b[ni][0] = __float_as_uint(Ws[cc][kk + tq]);
                b[ni][1] = __float_as_uint(Ws[cc][kk + tq + 4]);
            }
#pragma unroll
            for (int mi = 0; mi < 4; mi++)
#pragma unroll
                for (int ni = 0; ni < 4; ni++) {
                    asm volatile(
                        "mma.sync.aligned.m16n8k8.row.col.f32.tf32.tf32.f32 "
                        "{%0,%1,%2,%3}, {%4,%5,%6,%7}, {%8,%9}, {%0,%1,%2,%3};"
                        : "+f"(c[mi][ni][0]), "+f"(c[mi][ni][1]),
                          "+f"(c[mi][ni][2]), "+f"(c[mi][ni][3])
                        : "r"(a[mi][0]), "r"(a[mi][1]), "r"(a[mi][2]), "r"(a[mi][3]),
                          "r"(b[ni][0]), "r"(b[ni][1]));
                }
        }
        __syncthreads();
    }

    // ---- epilogue: bias (+ optional relu) ----
#pragma unroll
    for (int mi = 0; mi < 4; mi++) {
        int r0 = row0 + mw + mi * 16 + gq;
#pragma unroll
        for (int ni = 0; ni < 4; ni++) {
            int ccol = col0 + nw + ni * 8 + tq * 2;
            float b0 = bias[ccol], b1 = bias[ccol + 1];
            float v0 = c[mi][ni][0] + b0;
            float v1 = c[mi][ni][1] + b1;
            float v2 = c[mi][ni][2] + b0;
            float v3 = c[mi][ni][3] + b1;
            if (do_relu) {
                v0 = fmaxf(v0, 0.f); v1 = fmaxf(v1, 0.f);
                v2 = fmaxf(v2, 0.f); v3 = fmaxf(v3, 0.f);
            }
            if (r0 < nrows)
                *(float2*)&C[(size_t)r0 * mcols + ccol] = make_float2(v0, v1);
            if (r0 + 8 < nrows)
                *(float2*)&C[(size_t)(r0 + 8) * mcols + ccol] = make_float2(v2, v3);
        }
    }
}

// ---------------- max distance over edges ----------------------------------
__global__ void k_distmax(const int* __restrict__ ei, const float* __restrict__ pos)
{
    int i = blockIdx.x * blockDim.x + threadIdx.x;
    float m = 0.f;
    for (; i < NEDGES; i += gridDim.x * blockDim.x) {
        int s = ei[i], d = ei[NEDGES + i];
        float ax = pos[3 * s + 0] - pos[3 * d + 0];
        float ay = pos[3 * s + 1] - pos[3 * d + 1];
        float az = pos[3 * s + 2] - pos[3 * d + 2];
        m = fmaxf(m, sqrtf(ax * ax + ay * ay + az * az));
    }
#pragma unroll
    for (int o = 16; o; o >>= 1) m = fmaxf(m, __shfl_xor_sync(0xffffffffu, m, o));
    if ((threadIdx.x & 31) == 0) atomicMax(&g_distmax_bits, __float_as_uint(m));
}

// ---------------- edge scatter: agg[dst, k*128+f] += ab_k * hw[src, f] ------
__global__ void __launch_bounds__(256)
k_scatter(const int* __restrict__ ei, const float* __restrict__ pos,
          const float* __restrict__ vfp, const float* __restrict__ vparams)
{
    int e = (int)(((size_t)blockIdx.x * blockDim.x + threadIdx.x) >> 5);
    if (e >= NEDGES) return;
    const int lane = threadIdx.x & 31;

    int s = __ldg(&ei[e]);
    int d = __ldg(&ei[NEDGES + e]);

    float ax = pos[3 * s + 0] - pos[3 * d + 0];
    float ay = pos[3 * s + 1] - pos[3 * d + 1];
    float az = pos[3 * s + 2] - pos[3 * d + 2];
    float dist = sqrtf(ax * ax + ay * ay + az * az);
    float dmax = __uint_as_float(g_distmax_bits);
    float r    = dist / dmax;
    float inv  = 1.f / (dist + 1e-8f);
    float dsum = (ax + ay + az) * inv;
    float vf   = vfp[0];

    float ab[KOBS];
#pragma unroll
    for (int k = 0; k < KOBS; k++) {
        float v  = vf * fminf(r, vparams[k]);
        float g2 = 1.f - v * v + 1e-8f;
        ab[k] = sqrtf(g2) / (1.f + v * dsum);
    }

    const float4 hv = *(const float4*)&g_hw[(size_t)s * HDIM + lane * 4];
    float* base = &g_agg[(size_t)d * ZDIM + lane * 4];
#pragma unroll
    for (int k = 0; k < KOBS; k++) {
        float mx = ab[k] * hv.x, my = ab[k] * hv.y;
        float mz = ab[k] * hv.z, mw = ab[k] * hv.w;
        asm volatile("red.global.add.v4.f32 [%0], {%1, %2, %3, %4};"
                     :: "l"(base + k * HDIM), "f"(mx), "f"(my), "f"(mz), "f"(mw)
                     : "memory");
    }
}

// ---------------- BN column stats (mean/var over nodes) ---------------------
__global__ void k_colstats()
{
    int col = blockIdx.x * blockDim.x + threadIdx.x;    // grid.x = 2, block 256
    int r0 = blockIdx.y * 500;                          // grid.y = 100
    int r1 = r0 + 500; if (r1 > NNODES) r1 = NNODES;
    float s = 0.f, s2 = 0.f;
    for (int r = r0; r < r1; r++) {
        float v = g_agg[(size_t)r * ZDIM + col];
        s += v; s2 += v * v;
    }
    atomicAdd(&g_colsum[col],   (double)s);
    atomicAdd(&g_colsumsq[col], (double)s2);
}

__global__ void k_bnfinal(const float* __restrict__ bn_gamma,
                          const float* __restrict__ bn_beta,
                          const float* __restrict__ att)
{
    int c = blockIdx.x * blockDim.x + threadIdx.x;
    if (c >= ZDIM) return;
    float mean = (float)(g_colsum[c] * (1.0 / NNODES));
    float var  = (float)(g_colsumsq[c] * (1.0 / NNODES)) - mean * mean;
    float invs = 1.f / sqrtf(var + 1e-5f);
    float a  = att[c];                      // attention >= 0: fold through relu
    float sc = invs * bn_gamma[c];
    g_scale[c] = sc * a;
    g_shift[c] = (bn_beta[c] - mean * sc) * a;
}

// ---------------- LayerNorm (per row of z1 [N,256]) + relu, in place --------
__global__ void k_lnrelu(const float* __restrict__ gam, const float* __restrict__ bet)
{
    int row = blockIdx.x * (blockDim.x >> 5) + (threadIdx.x >> 5);
    if (row >= NNODES) return;
    int lane = threadIdx.x & 31;
    float* p = g_z1 + (size_t)row * MID;
    float v[8];
    float s = 0.f;
#pragma unroll
    for (int i = 0; i < 8; i++) { v[i] = p[lane + 32 * i]; s += v[i]; }
#pragma unroll
    for (int o = 16; o; o >>= 1) s += __shfl_xor_sync(0xffffffffu, s, o);
    float mean = s * (1.f / MID);
    float q = 0.f;
#pragma unroll
    for (int i = 0; i < 8; i++) { float t = v[i] - mean; q += t * t; }
#pragma unroll
    for (int o = 16; o; o >>= 1) q += __shfl_xor_sync(0xffffffffu, q, o);
    float inv = rsqrtf(q * (1.f / MID) + 1e-5f);
#pragma unroll
    for (int i = 0; i < 8; i++) {
        int c = lane + 32 * i;
        p[c] = fmaxf((v[i] - mean) * inv * gam[c] + bet[c], 0.f);
    }
}

// ---------------- launch -----------------------------------------------------
extern "C" void kernel_launch(void* const* d_in, const int* in_sizes, int n_in,
                              void* d_out, int out_size)
{
    const float* x        = (const float*)d_in[0];
    const int*   ei       = (const int*)  d_in[1];
    const float* pos      = (const float*)d_in[2];
    const float* W_ft     = (const float*)d_in[3];
    const float* b_ft     = (const float*)d_in[4];
    const float* W_conv   = (const float*)d_in[5];
    const float* b_conv   = (const float*)d_in[6];
    const float* vf       = (const float*)d_in[7];
    const float* vparams  = (const float*)d_in[8];
    const float* bn_gamma = (const float*)d_in[9];
    const float* bn_beta  = (const float*)d_in[10];
    const float* att      = (const float*)d_in[11];
    const float* W1       = (const float*)d_in[12];
    const float* b1       = (const float*)d_in[13];
    const float* ln_g     = (const float*)d_in[14];
    const float* ln_b     = (const float*)d_in[15];
    const float* W2       = (const float*)d_in[16];
    const float* b2       = (const float*)d_in[17];
    float* out = (float*)d_out;

    float *ph, *phw, *pagg, *pz1;
    cudaGetSymbolAddress((void**)&ph,   g_h);
    cudaGetSymbolAddress((void**)&phw,  g_hw);
    cudaGetSymbolAddress((void**)&pagg, g_agg);
    cudaGetSymbolAddress((void**)&pz1,  g_z1);

    const int ROWB = (NNODES + 127) / 128;  // 391

    // zero accumulators
    k_zero_misc<<<1, 512>>>();
    k_zero_agg<<<12800, 256>>>();

    // feature transform + conv linear (applied per node; gather commutes)
    k_gemm_tf32<<<dim3(1, ROWB), 256>>>(x,  W_ft,   b_ft,   ph,  NNODES, FDIM, HDIM, 1, 0);
    k_gemm_tf32<<<dim3(1, ROWB), 256>>>(ph, W_conv, b_conv, phw, NNODES, HDIM, HDIM, 0, 0);

    // edge geometry: global max distance, then scatter with aberration factors
    k_distmax<<<1024, 256>>>(ei, pos);
    {
        int blocks = (NEDGES + 7) / 8;   // one warp per edge, 8 warps/block
        k_scatter<<<blocks, 256>>>(ei, pos, vf, vparams);
    }

    // BatchNorm stats per (observer,feature) column; transform fused into W1 GEMM
    {
        dim3 g(2, 100);
        k_colstats<<<g, 256>>>();
    }
    k_bnfinal<<<2, 256>>>(bn_gamma, bn_beta, att);

    // MLP head: relu(BN(agg))*att @ W1^T -> LN -> relu -> @ W2^T
    k_gemm_tf32<<<dim3(MID / 128, ROWB), 256>>>(pagg, W1, b1, pz1, NNODES, ZDIM, MID, 0, 1);
    k_lnrelu<<<(NNODES + 7) / 8, 256>>>(ln_g, ln_b);
    k_gemm_tf32<<<dim3(ODIM / 128, ROWB), 256>>>(pz1, W2, b2, out, NNODES, MID, ODIM, 0, 0);
}

// round 3
// speedup vs baseline: 1.7617x; 1.0071x over previous
#include <cuda_runtime.h>
#include <math.h>
#include <stdint.h>

#define NNODES 50000
#define NEDGES 800000
#define FDIM 128
#define HDIM 128
#define ODIM 128
#define KOBS 4
#define ZDIM 512   /* K*H */
#define MID  256   /* 2*H */

// ---------------- scratch (device globals; no allocation allowed) ----------
__device__ __align__(16) float g_h  [(size_t)NNODES * HDIM];
__device__ __align__(16) float g_hw [(size_t)NNODES * HDIM];
__device__ __align__(16) float g_agg[(size_t)NNODES * ZDIM];
__device__ __align__(16) float g_z1 [(size_t)NNODES * MID];
__device__ double g_colsum  [ZDIM];
__device__ double g_colsumsq[ZDIM];
__device__ float  g_scale[ZDIM];   // bn scale * attention
__device__ float  g_shift[ZDIM];   // bn shift * attention
__device__ unsigned int g_distmax_bits;

// ---------------- zero kernels ---------------------------------------------
__global__ void k_zero_misc() {
    int t = threadIdx.x;
    if (t == 0) g_distmax_bits = 0u;
    if (t < ZDIM) { g_colsum[t] = 0.0; g_colsumsq[t] = 0.0; }
}

__global__ void k_zero_agg() {
    size_t i = (size_t)blockIdx.x * blockDim.x + threadIdx.x;
    size_t total = (size_t)NNODES * ZDIM / 4;
    float4 z = make_float4(0.f, 0.f, 0.f, 0.f);
    for (; i < total; i += (size_t)gridDim.x * blockDim.x)
        ((float4*)g_agg)[i] = z;
}

// ---------------- tf32 tensor-core GEMM ------------------------------------
// C[r,c] = sum_k A[r,k] * W[c,k] + bias[c]       (A @ W^T + b)
// A [nrows, kdim] row-major, W [mcols, kdim] row-major.
// CTA tile 128x128, BK=32, 8 warps each computing 64x32 via m16n8k8 tf32 mma.
// amode==1: A elements transformed on load: relu(a*g_scale[k] + g_shift[k])
// (used to fuse BatchNorm+relu+attention into the W1 GEMM).
__device__ __forceinline__ float to_tf32(float x) {
    float r;
    asm("cvt.rna.tf32.f32 %0, %1;" : "=f"(r) : "f"(x));
    return r;
}

#define ASTRIDE 36   /* pad: bank index = (4*row + k) % 32, conflict-free */

__global__ void __launch_bounds__(256, 2)
k_gemm_tf32(const float* __restrict__ A, const float* __restrict__ W,
            const float* __restrict__ bias, float* __restrict__ C,
            int nrows, int kdim, int mcols, int do_relu, int amode)
{
    __shared__ float As[128][ASTRIDE];
    __shared__ float Ws[128][ASTRIDE];
    const int tid  = threadIdx.x;
    const int warp = tid >> 5;
    const int lane = tid & 31;
    const int row0 = blockIdx.y * 128;
    const int col0 = blockIdx.x * 128;
    const int mw = (warp & 1) * 64;
    const int nw = (warp >> 1) * 32;
    const int gq = lane >> 2;      // group id 0..7
    const int tq = lane & 3;       // thread-in-group 0..3

    float c[4][4][4];
#pragma unroll
    for (int mi = 0; mi < 4; mi++)
#pragma unroll
        for (int ni = 0; ni < 4; ni++)
#pragma unroll
            for (int q = 0; q < 4; q++) c[mi][ni][q] = 0.f;

    for (int k0 = 0; k0 < kdim; k0 += 32) {
        // ---- load A tile (with optional BN transform) ----
#pragma unroll
        for (int t = 0; t < 4; t++) {
            int idx = tid + t * 256;     // 0..1023
            int r   = idx >> 3;          // 0..127
            int kv  = (idx & 7) * 4;     // 0,4,...,28
            float4 v = make_float4(0.f, 0.f, 0.f, 0.f);
            if (row0 + r < nrows)
                v = *(const float4*)&A[(size_t)(row0 + r) * kdim + k0 + kv];
            if (amode) {
                int cc = k0 + kv;
                v.x = fmaxf(fmaf(v.x, g_scale[cc + 0], g_shift[cc + 0]), 0.f);
                v.y = fmaxf(fmaf(v.y, g_scale[cc + 1], g_shift[cc + 1]), 0.f);
                v.z = fmaxf(fmaf(v.z, g_scale[cc + 2], g_shift[cc + 2]), 0.f);
                v.w = fmaxf(fmaf(v.w, g_scale[cc + 3], g_shift[cc + 3]), 0.f);
            }
            As[r][kv + 0] = to_tf32(v.x);
            As[r][kv + 1] = to_tf32(v.y);
            As[r][kv + 2] = to_tf32(v.z);
            As[r][kv + 3] = to_tf32(v.w);
        }
        // ---- load W tile ----
#pragma unroll
        for (int t = 0; t < 4; t++) {
            int idx = tid + t * 256;
            int r   = idx >> 3;
            int kv  = (idx & 7) * 4;
            float4 v = *(const float4*)&W[(size_t)(col0 + r) * kdim + k0 + kv];
            Ws[r][kv + 0] = to_tf32(v.x);
            Ws[r][kv + 1] = to_tf32(v.y);
            Ws[r][kv + 2] = to_tf32(v.z);
            Ws[r][kv + 3] = to_tf32(v.w);
        }
        __syncthreads();

#pragma unroll
        for (int j = 0; j < 4; j++) {
            const int kk = j * 8;
            uint32_t a[4][4], b[4][2];
#pragma unroll
            for (int mi = 0; mi < 4; mi++) {
                int r = mw + mi * 16 + gq;
                a[mi][0] = __float_as_uint(As[r    ][kk + tq]);
                a[mi][1] = __float_as_uint(As[r + 8][kk + tq]);
                a[mi][2] = __float_as_uint(As[r    ][kk + tq + 4]);
                a[mi][3] = __float_as_uint(As[r + 8][kk + tq + 4]);
            }
#pragma unroll
            for (int ni = 0; ni < 4; ni++) {
                int cc = nw + ni * 8 + gq;
                b[ni][0] = __float_as_uint(Ws[cc][kk + tq]);
                b[ni][1] = __float_as_uint(Ws[cc][kk + tq + 4]);
            }
#pragma unroll
            for (int mi = 0; mi < 4; mi++)
#pragma unroll
                for (int ni = 0; ni < 4; ni++) {
                    asm volatile(
                        "mma.sync.aligned.m16n8k8.row.col.f32.tf32.tf32.f32 "
                        "{%0,%1,%2,%3}, {%4,%5,%6,%7}, {%8,%9}, {%0,%1,%2,%3};"
                        : "+f"(c[mi][ni][0]), "+f"(c[mi][ni][1]),
                          "+f"(c[mi][ni][2]), "+f"(c[mi][ni][3])
                        : "r"(a[mi][0]), "r"(a[mi][1]), "r"(a[mi][2]), "r"(a[mi][3]),
                          "r"(b[ni][0]), "r"(b[ni][1]));
                }
        }
        __syncthreads();
    }

    // ---- epilogue: bias (+ optional relu) ----
#pragma unroll
    for (int mi = 0; mi < 4; mi++) {
        int r0 = row0 + mw + mi * 16 + gq;
#pragma unroll
        for (int ni = 0; ni < 4; ni++) {
            int ccol = col0 + nw + ni * 8 + tq * 2;
            float b0 = bias[ccol], b1 = bias[ccol + 1];
            float v0 = c[mi][ni][0] + b0;
            float v1 = c[mi][ni][1] + b1;
            float v2 = c[mi][ni][2] + b0;
            float v3 = c[mi][ni][3] + b1;
            if (do_relu) {
                v0 = fmaxf(v0, 0.f); v1 = fmaxf(v1, 0.f);
                v2 = fmaxf(v2, 0.f); v3 = fmaxf(v3, 0.f);
            }
            if (r0 < nrows)
                *(float2*)&C[(size_t)r0 * mcols + ccol] = make_float2(v0, v1);
            if (r0 + 8 < nrows)
                *(float2*)&C[(size_t)(r0 + 8) * mcols + ccol] = make_float2(v2, v3);
        }
    }
}

// ---------------- max distance over edges ----------------------------------
__global__ void k_distmax(const int* __restrict__ ei, const float* __restrict__ pos)
{
    int i = blockIdx.x * blockDim.x + threadIdx.x;
    float m = 0.f;
    for (; i < NEDGES; i += gridDim.x * blockDim.x) {
        int s = ei[i], d = ei[NEDGES + i];
        float ax = pos[3 * s + 0] - pos[3 * d + 0];
        float ay = pos[3 * s + 1] - pos[3 * d + 1];
        float az = pos[3 * s + 2] - pos[3 * d + 2];
        m = fmaxf(m, sqrtf(ax * ax + ay * ay + az * az));
    }
#pragma unroll
    for (int o = 16; o; o >>= 1) m = fmaxf(m, __shfl_xor_sync(0xffffffffu, m, o));
    if ((threadIdx.x & 31) == 0) atomicMax(&g_distmax_bits, __float_as_uint(m));
}

// ---------------- edge scatter: agg[dst, k*128+f] += ab_k * hw[src, f] ------
__global__ void __launch_bounds__(256)
k_scatter(const int* __restrict__ ei, const float* __restrict__ pos,
          const float* __restrict__ vfp, const float* __restrict__ vparams)
{
    int e = (int)(((size_t)blockIdx.x * blockDim.x + threadIdx.x) >> 5);
    if (e >= NEDGES) return;
    const int lane = threadIdx.x & 31;

    int s = __ldg(&ei[e]);
    int d = __ldg(&ei[NEDGES + e]);

    float ax = pos[3 * s + 0] - pos[3 * d + 0];
    float ay = pos[3 * s + 1] - pos[3 * d + 1];
    float az = pos[3 * s + 2] - pos[3 * d + 2];
    float dist = sqrtf(ax * ax + ay * ay + az * az);
    float dmax = __uint_as_float(g_distmax_bits);
    float r    = dist / dmax;
    float inv  = 1.f / (dist + 1e-8f);
    float dsum = (ax + ay + az) * inv;
    float vf   = vfp[0];

    float ab[KOBS];
#pragma unroll
    for (int k = 0; k < KOBS; k++) {
        float v  = vf * fminf(r, vparams[k]);
        float g2 = 1.f - v * v + 1e-8f;
        ab[k] = sqrtf(g2) / (1.f + v * dsum);
    }

    const float4 hv = *(const float4*)&g_hw[(size_t)s * HDIM + lane * 4];
    float* base = &g_agg[(size_t)d * ZDIM + lane * 4];
#pragma unroll
    for (int k = 0; k < KOBS; k++) {
        float mx = ab[k] * hv.x, my = ab[k] * hv.y;
        float mz = ab[k] * hv.z, mw = ab[k] * hv.w;
        asm volatile("red.global.add.v4.f32 [%0], {%1, %2, %3, %4};"
                     :: "l"(base + k * HDIM), "f"(mx), "f"(my), "f"(mz), "f"(mw)
                     : "memory");
    }
}

// ---------------- BN column stats (mean/var over nodes) ---------------------
__global__ void k_colstats()
{
    int col = blockIdx.x * blockDim.x + threadIdx.x;    // grid.x = 2, block 256
    int r0 = blockIdx.y * 500;                          // grid.y = 100
    int r1 = r0 + 500; if (r1 > NNODES) r1 = NNODES;
    float s = 0.f, s2 = 0.f;
    for (int r = r0; r < r1; r++) {
        float v = g_agg[(size_t)r * ZDIM + col];
        s += v; s2 += v * v;
    }
    atomicAdd(&g_colsum[col],   (double)s);
    atomicAdd(&g_colsumsq[col], (double)s2);
}

__global__ void k_bnfinal(const float* __restrict__ bn_gamma,
                          const float* __restrict__ bn_beta,
                          const float* __restrict__ att)
{
    int c = blockIdx.x * blockDim.x + threadIdx.x;
    if (c >= ZDIM) return;
    float mean = (float)(g_colsum[c] * (1.0 / NNODES));
    float var  = (float)(g_colsumsq[c] * (1.0 / NNODES)) - mean * mean;
    float invs = 1.f / sqrtf(var + 1e-5f);
    float a  = att[c];                      // attention >= 0: fold through relu
    float sc = invs * bn_gamma[c];
    g_scale[c] = sc * a;
    g_shift[c] = (bn_beta[c] - mean * sc) * a;
}

// ---------------- LayerNorm (per row of z1 [N,256]) + relu, in place --------
__global__ void k_lnrelu(const float* __restrict__ gam, const float* __restrict__ bet)
{
    int row = blockIdx.x * (blockDim.x >> 5) + (threadIdx.x >> 5);
    if (row >= NNODES) return;
    int lane = threadIdx.x & 31;
    float* p = g_z1 + (size_t)row * MID;
    float v[8];
    float s = 0.f;
#pragma unroll
    for (int i = 0; i < 8; i++) { v[i] = p[lane + 32 * i]; s += v[i]; }
#pragma unroll
    for (int o = 16; o; o >>= 1) s += __shfl_xor_sync(0xffffffffu, s, o);
    float mean = s * (1.f / MID);
    float q = 0.f;
#pragma unroll
    for (int i = 0; i < 8; i++) { float t = v[i] - mean; q += t * t; }
#pragma unroll
    for (int o = 16; o; o >>= 1) q += __shfl_xor_sync(0xffffffffu, q, o);
    float inv = rsqrtf(q * (1.f / MID) + 1e-5f);
#pragma unroll
    for (int i = 0; i < 8; i++) {
        int c = lane + 32 * i;
        p[c] = fmaxf((v[i] - mean) * inv * gam[c] + bet[c], 0.f);
    }
}

// ---------------- launch -----------------------------------------------------
extern "C" void kernel_launch(void* const* d_in, const int* in_sizes, int n_in,
                              void* d_out, int out_size)
{
    const float* x        = (const float*)d_in[0];
    const int*   ei       = (const int*)  d_in[1];
    const float* pos      = (const float*)d_in[2];
    const float* W_ft     = (const float*)d_in[3];
    const float* b_ft     = (const float*)d_in[4];
    const float* W_conv   = (const float*)d_in[5];
    const float* b_conv   = (const float*)d_in[6];
    const float* vf       = (const float*)d_in[7];
    const float* vparams  = (const float*)d_in[8];
    const float* bn_gamma = (const float*)d_in[9];
    const float* bn_beta  = (const float*)d_in[10];
    const float* att      = (const float*)d_in[11];
    const float* W1       = (const float*)d_in[12];
    const float* b1       = (const float*)d_in[13];
    const float* ln_g     = (const float*)d_in[14];
    const float* ln_b     = (const float*)d_in[15];
    const float* W2       = (const float*)d_in[16];
    const float* b2       = (const float*)d_in[17];
    float* out = (float*)d_out;

    float *ph, *phw, *pagg, *pz1;
    cudaGetSymbolAddress((void**)&ph,   g_h);
    cudaGetSymbolAddress((void**)&phw,  g_hw);
    cudaGetSymbolAddress((void**)&pagg, g_agg);
    cudaGetSymbolAddress((void**)&pz1,  g_z1);

    const int ROWB = (NNODES + 127) / 128;  // 391

    // zero accumulators
    k_zero_misc<<<1, 512>>>();
    k_zero_agg<<<12800, 256>>>();

    // feature transform + conv linear (applied per node; gather commutes)
    k_gemm_tf32<<<dim3(1, ROWB), 256>>>(x,  W_ft,   b_ft,   ph,  NNODES, FDIM, HDIM, 1, 0);
    k_gemm_tf32<<<dim3(1, ROWB), 256>>>(ph, W_conv, b_conv, phw, NNODES, HDIM, HDIM, 0, 0);

    // edge geometry: global max distance, then scatter with aberration factors
    k_distmax<<<1024, 256>>>(ei, pos);
    {
        int blocks = (NEDGES + 7) / 8;   // one warp per edge, 8 warps/block
        k_scatter<<<blocks, 256>>>(ei, pos, vf, vparams);
    }

    // BatchNorm stats per (observer,feature) column; transform fused into W1 GEMM
    {
        dim3 g(2, 100);
        k_colstats<<<g, 256>>>();
    }
    k_bnfinal<<<2, 256>>>(bn_gamma, bn_beta, att);

    // MLP head: relu(BN(agg))*att @ W1^T -> LN -> relu -> @ W2^T
    k_gemm_tf32<<<dim3(MID / 128, ROWB), 256>>>(pagg, W1, b1, pz1, NNODES, ZDIM, MID, 0, 1);
    k_lnrelu<<<(NNODES + 7) / 8, 256>>>(ln_g, ln_b);
    k_gemm_tf32<<<dim3(ODIM / 128, ROWB), 256>>>(pz1, W2, b2, out, NNODES, MID, ODIM, 0, 0);
}